// round 14
// baseline (speedup 1.0000x reference)
#include <cuda_runtime.h>

#define BSZ 2
#define TSEQ 2048
#define CDIM 1024
#define HN 16
#define DH 64

// Scratch (allocation-free rule: __device__ globals). All tf32 bit-patterns.
__device__ unsigned g_x32[(size_t)BSZ * TSEQ * CDIM];        // x as tf32
__device__ unsigned g_wa32[(size_t)CDIM * 3 * CDIM];         // w_attn as tf32
__device__ unsigned g_wp32[(size_t)CDIM * CDIM];             // w_proj as tf32
__device__ unsigned g_qkv[(size_t)BSZ * TSEQ * 3 * CDIM];    // qkv as tf32
__device__ unsigned g_y[(size_t)BSZ * TSEQ * CDIM];          // y as tf32

__device__ __forceinline__ unsigned f2tf32(float f) {
    unsigned r;
    asm("cvt.rna.tf32.f32 %0, %1;" : "=r"(r) : "f"(f));
    return r;
}

__device__ __forceinline__ void mma_tf32(float* c, const unsigned* a, const unsigned* b) {
    asm volatile(
        "mma.sync.aligned.m16n8k8.row.col.f32.tf32.tf32.f32 "
        "{%0,%1,%2,%3}, {%4,%5,%6,%7}, {%8,%9}, {%0,%1,%2,%3};"
        : "+f"(c[0]), "+f"(c[1]), "+f"(c[2]), "+f"(c[3])
        : "r"(a[0]), "r"(a[1]), "r"(a[2]), "r"(a[3]), "r"(b[0]), "r"(b[1]));
}

__device__ __forceinline__ void cp_async16(void* smem, const void* gmem) {
    unsigned saddr = (unsigned)__cvta_generic_to_shared(smem);
    asm volatile("cp.async.cg.shared.global [%0], [%1], 16;" :: "r"(saddr), "l"(gmem));
}
__device__ __forceinline__ void cp_commit() { asm volatile("cp.async.commit_group;"); }
__device__ __forceinline__ void cp_wait1()  { asm volatile("cp.async.wait_group 1;"); }
__device__ __forceinline__ void cp_wait0()  { asm volatile("cp.async.wait_group 0;"); }

__device__ __forceinline__ void ldm_x4(unsigned* r, const void* smem) {
    unsigned saddr = (unsigned)__cvta_generic_to_shared(smem);
    asm volatile("ldmatrix.sync.aligned.m8n8.x4.shared.b16 {%0,%1,%2,%3}, [%4];"
        : "=r"(r[0]), "=r"(r[1]), "=r"(r[2]), "=r"(r[3]) : "r"(saddr));
}

// ---------------------------------------------------------------------------
// fp32 -> tf32 pre-convert (vectorized)
// ---------------------------------------------------------------------------
__global__ __launch_bounds__(256) void cvt_tf32(
    const float* __restrict__ in, unsigned* __restrict__ out, int n4)
{
    int i = blockIdx.x * 256 + threadIdx.x;
    if (i < n4) {
        float4 v = *(const float4*)(in + (size_t)i * 4);
        uint4 u;
        u.x = f2tf32(v.x); u.y = f2tf32(v.y);
        u.z = f2tf32(v.z); u.w = f2tf32(v.w);
        *(uint4*)(out + (size_t)i * 4) = u;
    }
}

// ---------------------------------------------------------------------------
// tf32 tensor-core GEMM: 64x64 warp tiles (4 warps, CTA 128x128),
// 2-stage cp.async. C[M,N] = A[M,K] @ B[K,N] + bias[N].  (R11 winner, unchanged)
// ---------------------------------------------------------------------------
#define LDA 36
#define LDB 136
#define STG_A (128 * LDA)
#define STG_B (32 * LDB)
#define GEMM_SMEM (2 * (STG_A + STG_B))

template <bool OUT_TF32>
__global__ __launch_bounds__(128, 2) void gemm_tf32_bias(
    const unsigned* __restrict__ A, const unsigned* __restrict__ B,
    const float* __restrict__ bias, void* __restrict__ Cv,
    int M, int N, int K)
{
    extern __shared__ unsigned sg[];
    unsigned* sA = sg;                    // [2][128][LDA]
    unsigned* sB = sg + 2 * STG_A;        // [2][32][LDB]

    const int tid    = threadIdx.x;
    const int wid    = tid >> 5;          // 0..3
    const int lane   = tid & 31;
    const int g      = lane >> 2;
    const int t      = lane & 3;
    const int warp_m = wid >> 1;          // 0..1
    const int warp_n = wid & 1;           // 0..1
    const int bm     = blockIdx.y;
    const int bn     = blockIdx.x;

    float acc[4][8][4];
#pragma unroll
    for (int i = 0; i < 4; i++)
#pragma unroll
        for (int j = 0; j < 8; j++)
#pragma unroll
            for (int v = 0; v < 4; v++) acc[i][j][v] = 0.f;

    const int wm = warp_m * 64;
    const int wn = warp_n * 64;
    const int NK = K >> 5;

    const int rowL   = lane & 15;
    const int colOff = (lane >> 4) << 2;

    auto load_tiles = [&](int buf, int k0) {
        unsigned* dA = sA + buf * STG_A;
        unsigned* dB = sB + buf * STG_B;
#pragma unroll
        for (int it = 0; it < 8; it++) {
            int gidx = it * 128 + tid;
            int r = gidx >> 3, c = (gidx & 7) << 2;
            cp_async16(&dA[r * LDA + c], A + (size_t)(bm * 128 + r) * K + k0 + c);
        }
#pragma unroll
        for (int it = 0; it < 8; it++) {
            int gidx = it * 128 + tid;
            int r = gidx >> 5, c = (gidx & 31) << 2;
            cp_async16(&dB[r * LDB + c], B + (size_t)(k0 + r) * N + bn * 128 + c);
        }
        cp_commit();
    };

    load_tiles(0, 0);

    for (int i = 0; i < NK; i++) {
        if (i + 1 < NK) {
            load_tiles((i + 1) & 1, (i + 1) << 5);
            cp_wait1();
        } else {
            cp_wait0();
        }
        __syncthreads();

        const unsigned* cA = sA + (i & 1) * STG_A;
        const unsigned* cB = sB + (i & 1) * STG_B;

#pragma unroll
        for (int kk = 0; kk < 32; kk += 8) {
            unsigned af[4][4], bf[8][2];
#pragma unroll
            for (int mt = 0; mt < 4; mt++)
                ldm_x4(af[mt], &cA[(wm + mt * 16 + rowL) * LDA + kk + colOff]);
#pragma unroll
            for (int nt = 0; nt < 8; nt++) {
                int n0 = wn + nt * 8;
                bf[nt][0] = cB[(kk + t) * LDB + n0 + g];
                bf[nt][1] = cB[(kk + t + 4) * LDB + n0 + g];
            }
#pragma unroll
            for (int mt = 0; mt < 4; mt++)
#pragma unroll
                for (int nt = 0; nt < 8; nt++)
                    mma_tf32(acc[mt][nt], af[mt], bf[nt]);
        }
        __syncthreads();
    }

    // ---- epilogue: bias + store ----
#pragma unroll
    for (int nt = 0; nt < 8; nt++) {
        int col = bn * 128 + wn + nt * 8 + t * 2;
        float b0 = bias[col], b1 = bias[col + 1];
#pragma unroll
        for (int mt = 0; mt < 4; mt++) {
            int row0 = bm * 128 + wm + mt * 16 + g;
            float v00 = acc[mt][nt][0] + b0, v01 = acc[mt][nt][1] + b1;
            float v10 = acc[mt][nt][2] + b0, v11 = acc[mt][nt][3] + b1;
            if (OUT_TF32) {
                unsigned* C = (unsigned*)Cv;
                uint2 u0, u1;
                u0.x = f2tf32(v00); u0.y = f2tf32(v01);
                u1.x = f2tf32(v10); u1.y = f2tf32(v11);
                *(uint2*)(C + (size_t)row0 * N + col)       = u0;
                *(uint2*)(C + (size_t)(row0 + 8) * N + col) = u1;
            } else {
                float* C = (float*)Cv;
                float2 o0, o1;
                o0.x = v00; o0.y = v01;
                o1.x = v10; o1.y = v11;
                *(float2*)(C + (size_t)row0 * N + col)       = o0;
                *(float2*)(C + (size_t)(row0 + 8) * N + col) = o1;
            }
        }
    }
}

// ---------------------------------------------------------------------------
// Flash attention v4: CTA = 128 q-rows, 8 warps x m16, 32-key tiles.
// K triple-buffered cp.async; V transposed in smem (Vt[d][token], 3 buffers)
// so both K and V fragments load via ldmatrix.x4 (no scalar LDS in hot loop).
// smem 88.6 KB -> 2 CTAs/SM. Heavy-tiles-first.
// ---------------------------------------------------------------------------
#define LDQ 68
#define LDK 68
#define LDVT 36
#define KR 32
#define K_STRIDE (KR * LDK)           // one K buffer (32 keys x 68)
#define VT_STRIDE (64 * LDVT)         // one Vt buffer (64 d-rows x 36)
#define ATTN_SMEM (128 * LDQ + 3 * K_STRIDE + 3 * VT_STRIDE)   // 22144 u32

__global__ __launch_bounds__(256, 2) void attn_flash_mma(
    const unsigned* __restrict__ qkv, unsigned* __restrict__ y)
{
    extern __shared__ unsigned smu[];
    unsigned* sQ  = smu;                       // [128][LDQ]; reused as P staging
    unsigned* sK  = smu + 128 * LDQ;           // [3][KR][LDK]
    unsigned* sVt = sK + 3 * K_STRIDE;         // [3][64][LDVT]

    const int qb   = (int)gridDim.x - 1 - (int)blockIdx.x;   // heavy-first
    const int h    = blockIdx.y;
    const int b    = blockIdx.z;
    const int tid  = threadIdx.x;
    const int wid  = tid >> 5;
    const int lane = tid & 31;
    const int g    = lane >> 2;
    const int t    = lane & 3;
    const int wq   = wid * 16;

    const size_t rs = 3 * CDIM;
    const size_t baseQ = ((size_t)(b * TSEQ + qb * 128)) * rs + h * DH;

    // ---- load Q tile [128][64] (already tf32) ----
#pragma unroll
    for (int it = 0; it < 8; it++) {
        int idx = it * 256 + tid;
        int r = idx >> 4, c = (idx & 15) << 2;
        *(uint4*)&sQ[r * LDQ + c] = *(const uint4*)(qkv + baseQ + (size_t)r * rs + c);
    }

    const int nkb = 4 * qb + 4;              // 32-key tiles

    auto load_k = [&](int buf, int kb) {
        const size_t baseK = ((size_t)(b * TSEQ + kb * KR)) * rs + CDIM + h * DH;
        unsigned* dK = sK + buf * K_STRIDE;
#pragma unroll
        for (int it = 0; it < 2; it++) {
            int idx = it * 256 + tid;
            int r = idx >> 4, c = (idx & 15) << 2;
            cp_async16(&dK[r * LDK + c], qkv + baseK + (size_t)r * rs + c);
        }
        cp_commit();
    };

    // V: token-per-lane LDG (each thread grabs 8 d-values of one token)
    const int vTok   = tid & 31;
    const int vCbase = (tid >> 5) * 8;
    auto ldg_v = [&](int kb, uint4& a, uint4& c) {
        const size_t addr = ((size_t)(b * TSEQ + kb * KR + vTok)) * rs
                            + 2 * CDIM + h * DH + vCbase;
        a = *(const uint4*)(qkv + addr);
        c = *(const uint4*)(qkv + addr + 4);
    };
    auto sts_v = [&](int buf, const uint4& a, const uint4& c) {
        unsigned* dV = sVt + buf * VT_STRIDE;
        dV[(vCbase + 0) * LDVT + vTok] = a.x;
        dV[(vCbase + 1) * LDVT + vTok] = a.y;
        dV[(vCbase + 2) * LDVT + vTok] = a.z;
        dV[(vCbase + 3) * LDVT + vTok] = a.w;
        dV[(vCbase + 4) * LDVT + vTok] = c.x;
        dV[(vCbase + 5) * LDVT + vTok] = c.y;
        dV[(vCbase + 6) * LDVT + vTok] = c.z;
        dV[(vCbase + 7) * LDVT + vTok] = c.w;
    };

    // prologue: K(0), K(1) in flight; Vt(0) staged; vreg holds V(1)
    uint4 va, vc;
    load_k(0, 0);
    load_k(1, 1);
    ldg_v(0, va, vc);
    sts_v(0, va, vc);
    ldg_v(1, va, vc);
    __syncthreads();   // sQ + Vt0 visible

    // ---- Q fragments into registers ----
    const int rowL   = lane & 15;
    const int colOff = (lane >> 4) << 2;
    unsigned qf[8][4];
#pragma unroll
    for (int kk = 0; kk < 8; kk++)
        ldm_x4(qf[kk], &sQ[(wq + rowL) * LDQ + kk * 8 + colOff]);

    unsigned* sP = sQ + wq * LDQ;   // per-warp P staging [16][LDQ] (cols 0..31)

    float o[8][4];
#pragma unroll
    for (int nt = 0; nt < 8; nt++)
#pragma unroll
        for (int j = 0; j < 4; j++) o[nt][j] = 0.f;
    float m0 = -1e30f, m1 = -1e30f, l0 = 0.f, l1 = 0.f;

    const int rowW = qb * 128 + wq;
    const int r0g  = rowW + g;
    const int r1g  = rowW + 8 + g;

    // ldmatrix.x4 lane addressing for K/Vt pair-fragments
    const int kRow = ((lane >> 4) & 1) * 8 + (lane & 7);
    const int kCol = ((lane >> 3) & 1) * 4;

    for (int kb = 0; kb < nkb; kb++) {
        if (kb + 2 < nkb) load_k((kb + 2) % 3, kb + 2);
        if (kb + 1 < nkb) cp_wait1(); else cp_wait0();
        __syncthreads();

        const bool active = (rowW + 15 >= kb * KR);
        if (active) {
            const unsigned* cK  = sK  + (kb % 3) * K_STRIDE;
            const unsigned* cVt = sVt + (kb % 3) * VT_STRIDE;

            // ---- S = Q @ K^T  (16 x 32), K frags via ldm_x4 pairs ----
            float s[4][4];
#pragma unroll
            for (int nt = 0; nt < 4; nt++)
#pragma unroll
                for (int j = 0; j < 4; j++) s[nt][j] = 0.f;

#pragma unroll
            for (int kk = 0; kk < 8; kk++) {
#pragma unroll
                for (int ntp = 0; ntp < 2; ntp++) {
                    unsigned bfk[4];
                    ldm_x4(bfk, &cK[(ntp * 16 + kRow) * LDK + kk * 8 + kCol]);
                    mma_tf32(s[2 * ntp],     qf[kk], bfk);
                    mma_tf32(s[2 * ntp + 1], qf[kk], bfk + 2);
                }
            }

            // ---- scale + causal mask ----
            const float scale = 0.125f;
            if (kb * KR + KR - 1 > rowW) {
#pragma unroll
                for (int nt = 0; nt < 4; nt++) {
                    int c0 = kb * KR + nt * 8 + 2 * t;
                    s[nt][0] = (c0     <= r0g) ? s[nt][0] * scale : -1e30f;
                    s[nt][1] = (c0 + 1 <= r0g) ? s[nt][1] * scale : -1e30f;
                    s[nt][2] = (c0     <= r1g) ? s[nt][2] * scale : -1e30f;
                    s[nt][3] = (c0 + 1 <= r1g) ? s[nt][3] * scale : -1e30f;
                }
            } else {
#pragma unroll
                for (int nt = 0; nt < 4; nt++)
#pragma unroll
                    for (int j = 0; j < 4; j++) s[nt][j] *= scale;
            }

            // ---- online softmax ----
            float mx0 = -1e30f, mx1 = -1e30f;
#pragma unroll
            for (int nt = 0; nt < 4; nt++) {
                mx0 = fmaxf(mx0, fmaxf(s[nt][0], s[nt][1]));
                mx1 = fmaxf(mx1, fmaxf(s[nt][2], s[nt][3]));
            }
            mx0 = fmaxf(mx0, __shfl_xor_sync(0xffffffffu, mx0, 1));
            mx0 = fmaxf(mx0, __shfl_xor_sync(0xffffffffu, mx0, 2));
            mx1 = fmaxf(mx1, __shfl_xor_sync(0xffffffffu, mx1, 1));
            mx1 = fmaxf(mx1, __shfl_xor_sync(0xffffffffu, mx1, 2));

            float mn0 = fmaxf(m0, mx0), mn1 = fmaxf(m1, mx1);
            float a0 = __expf(m0 - mn0), a1 = __expf(m1 - mn1);
            m0 = mn0; m1 = mn1;

            float sum0 = 0.f, sum1 = 0.f;
#pragma unroll
            for (int nt = 0; nt < 4; nt++) {
                s[nt][0] = __expf(s[nt][0] - mn0);
                s[nt][1] = __expf(s[nt][1] - mn0);
                s[nt][2] = __expf(s[nt][2] - mn1);
                s[nt][3] = __expf(s[nt][3] - mn1);
                sum0 += s[nt][0] + s[nt][1];
                sum1 += s[nt][2] + s[nt][3];
            }
            sum0 += __shfl_xor_sync(0xffffffffu, sum0, 1);
            sum0 += __shfl_xor_sync(0xffffffffu, sum0, 2);
            sum1 += __shfl_xor_sync(0xffffffffu, sum1, 1);
            sum1 += __shfl_xor_sync(0xffffffffu, sum1, 2);
            l0 = l0 * a0 + sum0;
            l1 = l1 * a1 + sum1;

#pragma unroll
            for (int nt = 0; nt < 8; nt++) {
                o[nt][0] *= a0; o[nt][1] *= a0;
                o[nt][2] *= a1; o[nt][3] *= a1;
            }

            // ---- stage P (tf32) into per-warp smem [16][32] ----
            __syncwarp();
#pragma unroll
            for (int nt = 0; nt < 4; nt++) {
                int c0 = nt * 8 + 2 * t;
                uint2 u0, u1;
                u0.x = f2tf32(s[nt][0]); u0.y = f2tf32(s[nt][1]);
                u1.x = f2tf32(s[nt][2]); u1.y = f2tf32(s[nt][3]);
                *(uint2*)&sP[g * LDQ + c0]       = u0;
                *(uint2*)&sP[(8 + g) * LDQ + c0] = u1;
            }
            __syncwarp();

            // ---- O += P @ V : V frags via ldm_x4 from Vt ----
#pragma unroll
            for (int kk = 0; kk < 4; kk++) {
                unsigned pf[4];
                ldm_x4(pf, &sP[rowL * LDQ + kk * 8 + colOff]);
#pragma unroll
                for (int ntp = 0; ntp < 4; ntp++) {
                    unsigned bfv[4];
                    ldm_x4(bfv, &cVt[(ntp * 16 + kRow) * LDVT + kk * 8 + kCol]);
                    mma_tf32(o[2 * ntp],     pf, bfv);
                    mma_tf32(o[2 * ntp + 1], pf, bfv + 2);
                }
            }
        }

        // stage next V tile, prefetch the one after into regs
        if (kb + 1 < nkb) sts_v((kb + 1) % 3, va, vc);
        if (kb + 2 < nkb) ldg_v(kb + 2, va, vc);
        __syncthreads();
    }

    // ---- epilogue: normalize, write y (tf32 bits) ----
    float inv0 = 1.0f / l0, inv1 = 1.0f / l1;
    const size_t yr0 = ((size_t)(b * TSEQ) + r0g) * CDIM + h * DH;
    const size_t yr1 = ((size_t)(b * TSEQ) + r1g) * CDIM + h * DH;
#pragma unroll
    for (int nt = 0; nt < 8; nt++) {
        int c0 = nt * 8 + 2 * t;
        uint2 v0, v1;
        v0.x = f2tf32(o[nt][0] * inv0); v0.y = f2tf32(o[nt][1] * inv0);
        v1.x = f2tf32(o[nt][2] * inv1); v1.y = f2tf32(o[nt][3] * inv1);
        *(uint2*)(y + yr0 + c0) = v0;
        *(uint2*)(y + yr1 + c0) = v1;
    }
}

// ---------------------------------------------------------------------------
extern "C" void kernel_launch(void* const* d_in, const int* in_sizes, int n_in,
                              void* d_out, int out_size)
{
    const float* x      = (const float*)d_in[0];
    const float* w_attn = (const float*)d_in[1];
    const float* b_attn = (const float*)d_in[2];
    const float* w_proj = (const float*)d_in[3];
    const float* b_proj = (const float*)d_in[4];
    float* out = (float*)d_out;

    unsigned *x32, *wa32, *wp32, *qkv, *yb;
    cudaGetSymbolAddress((void**)&x32, g_x32);
    cudaGetSymbolAddress((void**)&wa32, g_wa32);
    cudaGetSymbolAddress((void**)&wp32, g_wp32);
    cudaGetSymbolAddress((void**)&qkv, g_qkv);
    cudaGetSymbolAddress((void**)&yb, g_y);

    const int smem_gemm = GEMM_SMEM * (int)sizeof(unsigned);   // 71680 B
    const int smem_attn = ATTN_SMEM * (int)sizeof(unsigned);   // 88576 B
    cudaFuncSetAttribute(gemm_tf32_bias<true>,
                         cudaFuncAttributeMaxDynamicSharedMemorySize, smem_gemm);
    cudaFuncSetAttribute(gemm_tf32_bias<false>,
                         cudaFuncAttributeMaxDynamicSharedMemorySize, smem_gemm);
    cudaFuncSetAttribute(attn_flash_mma,
                         cudaFuncAttributeMaxDynamicSharedMemorySize, smem_attn);

    const int M = BSZ * TSEQ;   // 4096

    // 0) pre-convert inputs to tf32
    const int nx  = M * CDIM / 4;
    const int nwa = CDIM * 3 * CDIM / 4;
    const int nwp = CDIM * CDIM / 4;
    cvt_tf32<<<(nx  + 255) / 256, 256>>>(x,      x32,  nx);
    cvt_tf32<<<(nwa + 255) / 256, 256>>>(w_attn, wa32, nwa);
    cvt_tf32<<<(nwp + 255) / 256, 256>>>(w_proj, wp32, nwp);

    // 1) qkv = x @ w_attn + b_attn     [4096, 3072]  (tf32 out)
    gemm_tf32_bias<true><<<dim3((3 * CDIM) / 128, M / 128), 128, smem_gemm>>>(
        x32, wa32, b_attn, qkv, M, 3 * CDIM, CDIM);

    // 2) flash attention -> y (tf32)   [4096, 1024]
    attn_flash_mma<<<dim3(TSEQ / 128, HN, BSZ), 256, smem_attn>>>(qkv, yb);

    // 3) out = y @ w_proj + b_proj     [4096, 1024]  (fp32 out)
    gemm_tf32_bias<false><<<dim3(CDIM / 128, M / 128), 128, smem_gemm>>>(
        yb, wp32, b_proj, out, M, CDIM, CDIM);
}

// round 15
// speedup vs baseline: 1.1185x; 1.1185x over previous
#include <cuda_runtime.h>

#define BSZ 2
#define TSEQ 2048
#define CDIM 1024
#define HN 16
#define DH 64

// Scratch (allocation-free rule: __device__ globals). All tf32 bit-patterns.
__device__ unsigned g_x32[(size_t)BSZ * TSEQ * CDIM];        // x as tf32
__device__ unsigned g_wa32[(size_t)CDIM * 3 * CDIM];         // w_attn as tf32
__device__ unsigned g_wp32[(size_t)CDIM * CDIM];             // w_proj as tf32
__device__ unsigned g_qkv[(size_t)BSZ * TSEQ * 3 * CDIM];    // qkv as tf32
__device__ unsigned g_y[(size_t)BSZ * TSEQ * CDIM];          // y as tf32

__device__ __forceinline__ unsigned f2tf32(float f) {
    unsigned r;
    asm("cvt.rna.tf32.f32 %0, %1;" : "=r"(r) : "f"(f));
    return r;
}

__device__ __forceinline__ void mma_tf32(float* c, const unsigned* a, const unsigned* b) {
    asm volatile(
        "mma.sync.aligned.m16n8k8.row.col.f32.tf32.tf32.f32 "
        "{%0,%1,%2,%3}, {%4,%5,%6,%7}, {%8,%9}, {%0,%1,%2,%3};"
        : "+f"(c[0]), "+f"(c[1]), "+f"(c[2]), "+f"(c[3])
        : "r"(a[0]), "r"(a[1]), "r"(a[2]), "r"(a[3]), "r"(b[0]), "r"(b[1]));
}

__device__ __forceinline__ void cp_async16(void* smem, const void* gmem) {
    unsigned saddr = (unsigned)__cvta_generic_to_shared(smem);
    asm volatile("cp.async.cg.shared.global [%0], [%1], 16;" :: "r"(saddr), "l"(gmem));
}
__device__ __forceinline__ void cp_commit() { asm volatile("cp.async.commit_group;"); }
__device__ __forceinline__ void cp_wait1()  { asm volatile("cp.async.wait_group 1;"); }
__device__ __forceinline__ void cp_wait0()  { asm volatile("cp.async.wait_group 0;"); }

__device__ __forceinline__ void ldm_x4(unsigned* r, const void* smem) {
    unsigned saddr = (unsigned)__cvta_generic_to_shared(smem);
    asm volatile("ldmatrix.sync.aligned.m8n8.x4.shared.b16 {%0,%1,%2,%3}, [%4];"
        : "=r"(r[0]), "=r"(r[1]), "=r"(r[2]), "=r"(r[3]) : "r"(saddr));
}
__device__ __forceinline__ void ldm_x2(unsigned* r, const void* smem) {
    unsigned saddr = (unsigned)__cvta_generic_to_shared(smem);
    asm volatile("ldmatrix.sync.aligned.m8n8.x2.shared.b16 {%0,%1}, [%2];"
        : "=r"(r[0]), "=r"(r[1]) : "r"(saddr));
}

// ---------------------------------------------------------------------------
// fp32 -> tf32 pre-convert (vectorized)
// ---------------------------------------------------------------------------
__global__ __launch_bounds__(256) void cvt_tf32(
    const float* __restrict__ in, unsigned* __restrict__ out, int n4)
{
    int i = blockIdx.x * 256 + threadIdx.x;
    if (i < n4) {
        float4 v = *(const float4*)(in + (size_t)i * 4);
        uint4 u;
        u.x = f2tf32(v.x); u.y = f2tf32(v.y);
        u.z = f2tf32(v.z); u.w = f2tf32(v.w);
        *(uint4*)(out + (size_t)i * 4) = u;
    }
}

// ---------------------------------------------------------------------------
// tf32 tensor-core GEMM: 64x64 warp tiles (4 warps, CTA 128x128),
// 2-stage cp.async. C[M,N] = A[M,K] @ B[K,N] + bias[N].  (R11 winner, unchanged)
// ---------------------------------------------------------------------------
#define LDA 36
#define LDB 136
#define STG_A (128 * LDA)
#define STG_B (32 * LDB)
#define GEMM_SMEM (2 * (STG_A + STG_B))

template <bool OUT_TF32>
__global__ __launch_bounds__(128, 2) void gemm_tf32_bias(
    const unsigned* __restrict__ A, const unsigned* __restrict__ B,
    const float* __restrict__ bias, void* __restrict__ Cv,
    int M, int N, int K)
{
    extern __shared__ unsigned sg[];
    unsigned* sA = sg;                    // [2][128][LDA]
    unsigned* sB = sg + 2 * STG_A;        // [2][32][LDB]

    const int tid    = threadIdx.x;
    const int wid    = tid >> 5;          // 0..3
    const int lane   = tid & 31;
    const int g      = lane >> 2;
    const int t      = lane & 3;
    const int warp_m = wid >> 1;          // 0..1
    const int warp_n = wid & 1;           // 0..1
    const int bm     = blockIdx.y;
    const int bn     = blockIdx.x;

    float acc[4][8][4];
#pragma unroll
    for (int i = 0; i < 4; i++)
#pragma unroll
        for (int j = 0; j < 8; j++)
#pragma unroll
            for (int v = 0; v < 4; v++) acc[i][j][v] = 0.f;

    const int wm = warp_m * 64;
    const int wn = warp_n * 64;
    const int NK = K >> 5;

    const int rowL   = lane & 15;
    const int colOff = (lane >> 4) << 2;

    auto load_tiles = [&](int buf, int k0) {
        unsigned* dA = sA + buf * STG_A;
        unsigned* dB = sB + buf * STG_B;
#pragma unroll
        for (int it = 0; it < 8; it++) {
            int gidx = it * 128 + tid;
            int r = gidx >> 3, c = (gidx & 7) << 2;
            cp_async16(&dA[r * LDA + c], A + (size_t)(bm * 128 + r) * K + k0 + c);
        }
#pragma unroll
        for (int it = 0; it < 8; it++) {
            int gidx = it * 128 + tid;
            int r = gidx >> 5, c = (gidx & 31) << 2;
            cp_async16(&dB[r * LDB + c], B + (size_t)(k0 + r) * N + bn * 128 + c);
        }
        cp_commit();
    };

    load_tiles(0, 0);

    for (int i = 0; i < NK; i++) {
        if (i + 1 < NK) {
            load_tiles((i + 1) & 1, (i + 1) << 5);
            cp_wait1();
        } else {
            cp_wait0();
        }
        __syncthreads();

        const unsigned* cA = sA + (i & 1) * STG_A;
        const unsigned* cB = sB + (i & 1) * STG_B;

#pragma unroll
        for (int kk = 0; kk < 32; kk += 8) {
            unsigned af[4][4], bf[8][2];
#pragma unroll
            for (int mt = 0; mt < 4; mt++)
                ldm_x4(af[mt], &cA[(wm + mt * 16 + rowL) * LDA + kk + colOff]);
#pragma unroll
            for (int nt = 0; nt < 8; nt++) {
                int n0 = wn + nt * 8;
                bf[nt][0] = cB[(kk + t) * LDB + n0 + g];
                bf[nt][1] = cB[(kk + t + 4) * LDB + n0 + g];
            }
#pragma unroll
            for (int mt = 0; mt < 4; mt++)
#pragma unroll
                for (int nt = 0; nt < 8; nt++)
                    mma_tf32(acc[mt][nt], af[mt], bf[nt]);
        }
        __syncthreads();
    }

    // ---- epilogue: bias + store ----
#pragma unroll
    for (int nt = 0; nt < 8; nt++) {
        int col = bn * 128 + wn + nt * 8 + t * 2;
        float b0 = bias[col], b1 = bias[col + 1];
#pragma unroll
        for (int mt = 0; mt < 4; mt++) {
            int row0 = bm * 128 + wm + mt * 16 + g;
            float v00 = acc[mt][nt][0] + b0, v01 = acc[mt][nt][1] + b1;
            float v10 = acc[mt][nt][2] + b0, v11 = acc[mt][nt][3] + b1;
            if (OUT_TF32) {
                unsigned* C = (unsigned*)Cv;
                uint2 u0, u1;
                u0.x = f2tf32(v00); u0.y = f2tf32(v01);
                u1.x = f2tf32(v10); u1.y = f2tf32(v11);
                *(uint2*)(C + (size_t)row0 * N + col)       = u0;
                *(uint2*)(C + (size_t)(row0 + 8) * N + col) = u1;
            } else {
                float* C = (float*)Cv;
                float2 o0, o1;
                o0.x = v00; o0.y = v01;
                o1.x = v10; o1.y = v11;
                *(float2*)(C + (size_t)row0 * N + col)       = o0;
                *(float2*)(C + (size_t)(row0 + 8) * N + col) = o1;
            }
        }
    }
}

// ---------------------------------------------------------------------------
// Flash attention v5: CTA = 128 q-rows, 4 warps x m32 (2 x m16 sub-tiles),
// 64-key tiles double-buffered. Each K/V fragment feeds 2 MMAs -> smem
// traffic per tile halved vs m16. smem 106.5 KB -> 2 CTAs/SM. Heavy-first.
// ---------------------------------------------------------------------------
#define LDQ 68
#define LDK 68
#define LDV 72
#define ATTN_SMEM (128 * LDQ + 2 * 64 * LDK + 2 * 64 * LDV)   // 26624 u32

__global__ __launch_bounds__(128, 2) void attn_flash_mma(
    const unsigned* __restrict__ qkv, unsigned* __restrict__ y)
{
    extern __shared__ unsigned smu[];
    unsigned* sQ = smu;                      // [128][LDQ]; reused as P staging
    unsigned* sK = smu + 128 * LDQ;          // [2][64][LDK]
    unsigned* sV = sK + 2 * 64 * LDK;        // [2][64][LDV]

    const int qb   = (int)gridDim.x - 1 - (int)blockIdx.x;   // heavy-first
    const int h    = blockIdx.y;
    const int b    = blockIdx.z;
    const int tid  = threadIdx.x;
    const int wid  = tid >> 5;               // 0..3
    const int lane = tid & 31;
    const int g    = lane >> 2;
    const int t    = lane & 3;
    const int wq   = wid * 32;               // warp's 32-row slice

    const size_t rs = 3 * CDIM;
    const size_t baseQ = ((size_t)(b * TSEQ + qb * 128)) * rs + h * DH;

    // ---- load Q tile [128][64] (already tf32), 128 threads ----
#pragma unroll
    for (int it = 0; it < 16; it++) {
        int idx = it * 128 + tid;
        int r = idx >> 4, c = (idx & 15) << 2;
        *(uint4*)&sQ[r * LDQ + c] = *(const uint4*)(qkv + baseQ + (size_t)r * rs + c);
    }

    const int nkb = 2 * qb + 2;              // 64-key tiles

    auto load_kv = [&](int buf, int kb) {
        const size_t baseK = ((size_t)(b * TSEQ + kb * 64)) * rs + CDIM + h * DH;
        unsigned* dK = sK + buf * 64 * LDK;
        unsigned* dV = sV + buf * 64 * LDV;
#pragma unroll
        for (int it = 0; it < 8; it++) {
            int idx = it * 128 + tid;
            int r = idx >> 4, c = (idx & 15) << 2;
            cp_async16(&dK[r * LDK + c], qkv + baseK + (size_t)r * rs + c);
            cp_async16(&dV[r * LDV + c], qkv + baseK + CDIM + (size_t)r * rs + c);
        }
        cp_commit();
    };

    load_kv(0, 0);
    __syncthreads();

    // ---- Q fragments into registers: 2 m16 sub-tiles ----
    const int rowL   = lane & 15;
    const int colOff = (lane >> 4) << 2;
    unsigned qf[8][2][4];
#pragma unroll
    for (int kk = 0; kk < 8; kk++)
#pragma unroll
        for (int mt = 0; mt < 2; mt++)
            ldm_x4(qf[kk][mt], &sQ[(wq + mt * 16 + rowL) * LDQ + kk * 8 + colOff]);

    unsigned* sP = sQ + wq * LDQ;   // per-warp P staging [32][LDQ]

    float o[2][8][4];
#pragma unroll
    for (int mt = 0; mt < 2; mt++)
#pragma unroll
        for (int nt = 0; nt < 8; nt++)
#pragma unroll
            for (int j = 0; j < 4; j++) o[mt][nt][j] = 0.f;
    float mS[2][2], lS[2][2];
#pragma unroll
    for (int mt = 0; mt < 2; mt++) {
        mS[mt][0] = -1e30f; mS[mt][1] = -1e30f;
        lS[mt][0] = 0.f;    lS[mt][1] = 0.f;
    }

    const int rowW = qb * 128 + wq;          // warp's min global q row
    const int rowK   = lane & 7;
    const int colKof = (lane & 8) ? 4 : 0;

    for (int kb = 0; kb < nkb; kb++) {
        if (kb + 1 < nkb) {
            load_kv((kb + 1) & 1, kb + 1);
            cp_wait1();
        } else {
            cp_wait0();
        }
        __syncthreads();

        const bool active = (rowW + 31 >= kb * 64);
        if (active) {
            const unsigned* cK = sK + (kb & 1) * 64 * LDK;
            const unsigned* cV = sV + (kb & 1) * 64 * LDV;

            // ---- S = Q @ K^T : K frag shared across 2 m-tiles ----
            float s[2][8][4];
#pragma unroll
            for (int mt = 0; mt < 2; mt++)
#pragma unroll
                for (int nt = 0; nt < 8; nt++)
#pragma unroll
                    for (int j = 0; j < 4; j++) s[mt][nt][j] = 0.f;

#pragma unroll
            for (int kk = 0; kk < 8; kk++) {
#pragma unroll
                for (int nt = 0; nt < 8; nt++) {
                    unsigned bf[2];
                    ldm_x2(bf, &cK[(nt * 8 + rowK) * LDK + kk * 8 + colKof]);
                    mma_tf32(s[0][nt], qf[kk][0], bf);
                    mma_tf32(s[1][nt], qf[kk][1], bf);
                }
            }

            // ---- scale + causal mask ----
            const float scale = 0.125f;
            if (kb * 64 + 63 > rowW) {
#pragma unroll
                for (int mt = 0; mt < 2; mt++) {
                    int r0 = rowW + mt * 16 + g;
                    int r1 = r0 + 8;
#pragma unroll
                    for (int nt = 0; nt < 8; nt++) {
                        int c0 = kb * 64 + nt * 8 + 2 * t;
                        s[mt][nt][0] = (c0     <= r0) ? s[mt][nt][0] * scale : -1e30f;
                        s[mt][nt][1] = (c0 + 1 <= r0) ? s[mt][nt][1] * scale : -1e30f;
                        s[mt][nt][2] = (c0     <= r1) ? s[mt][nt][2] * scale : -1e30f;
                        s[mt][nt][3] = (c0 + 1 <= r1) ? s[mt][nt][3] * scale : -1e30f;
                    }
                }
            } else {
#pragma unroll
                for (int mt = 0; mt < 2; mt++)
#pragma unroll
                    for (int nt = 0; nt < 8; nt++)
#pragma unroll
                        for (int j = 0; j < 4; j++) s[mt][nt][j] *= scale;
            }

            // ---- online softmax (4 row-slots per thread) ----
#pragma unroll
            for (int mt = 0; mt < 2; mt++) {
                float mx0 = -1e30f, mx1 = -1e30f;
#pragma unroll
                for (int nt = 0; nt < 8; nt++) {
                    mx0 = fmaxf(mx0, fmaxf(s[mt][nt][0], s[mt][nt][1]));
                    mx1 = fmaxf(mx1, fmaxf(s[mt][nt][2], s[mt][nt][3]));
                }
                mx0 = fmaxf(mx0, __shfl_xor_sync(0xffffffffu, mx0, 1));
                mx0 = fmaxf(mx0, __shfl_xor_sync(0xffffffffu, mx0, 2));
                mx1 = fmaxf(mx1, __shfl_xor_sync(0xffffffffu, mx1, 1));
                mx1 = fmaxf(mx1, __shfl_xor_sync(0xffffffffu, mx1, 2));

                float mn0 = fmaxf(mS[mt][0], mx0), mn1 = fmaxf(mS[mt][1], mx1);
                float a0 = __expf(mS[mt][0] - mn0), a1 = __expf(mS[mt][1] - mn1);
                mS[mt][0] = mn0; mS[mt][1] = mn1;

                float sum0 = 0.f, sum1 = 0.f;
#pragma unroll
                for (int nt = 0; nt < 8; nt++) {
                    s[mt][nt][0] = __expf(s[mt][nt][0] - mn0);
                    s[mt][nt][1] = __expf(s[mt][nt][1] - mn0);
                    s[mt][nt][2] = __expf(s[mt][nt][2] - mn1);
                    s[mt][nt][3] = __expf(s[mt][nt][3] - mn1);
                    sum0 += s[mt][nt][0] + s[mt][nt][1];
                    sum1 += s[mt][nt][2] + s[mt][nt][3];
                }
                sum0 += __shfl_xor_sync(0xffffffffu, sum0, 1);
                sum0 += __shfl_xor_sync(0xffffffffu, sum0, 2);
                sum1 += __shfl_xor_sync(0xffffffffu, sum1, 1);
                sum1 += __shfl_xor_sync(0xffffffffu, sum1, 2);
                lS[mt][0] = lS[mt][0] * a0 + sum0;
                lS[mt][1] = lS[mt][1] * a1 + sum1;

#pragma unroll
                for (int nt = 0; nt < 8; nt++) {
                    o[mt][nt][0] *= a0; o[mt][nt][1] *= a0;
                    o[mt][nt][2] *= a1; o[mt][nt][3] *= a1;
                }
            }

            // ---- stage P (tf32) into per-warp smem [32][LDQ] ----
            __syncwarp();
#pragma unroll
            for (int mt = 0; mt < 2; mt++)
#pragma unroll
                for (int nt = 0; nt < 8; nt++) {
                    int c0 = nt * 8 + 2 * t;
                    uint2 u0, u1;
                    u0.x = f2tf32(s[mt][nt][0]); u0.y = f2tf32(s[mt][nt][1]);
                    u1.x = f2tf32(s[mt][nt][2]); u1.y = f2tf32(s[mt][nt][3]);
                    *(uint2*)&sP[(mt * 16 + g) * LDQ + c0]     = u0;
                    *(uint2*)&sP[(mt * 16 + 8 + g) * LDQ + c0] = u1;
                }
            __syncwarp();

            // ---- O += P @ V : V frag shared across 2 m-tiles ----
#pragma unroll
            for (int kk = 0; kk < 8; kk++) {
                unsigned pf[2][4];
                ldm_x4(pf[0], &sP[rowL * LDQ + kk * 8 + colOff]);
                ldm_x4(pf[1], &sP[(16 + rowL) * LDQ + kk * 8 + colOff]);
#pragma unroll
                for (int nt = 0; nt < 8; nt++) {
                    unsigned bf[2];
                    bf[0] = cV[(kk * 8 + t) * LDV + nt * 8 + g];
                    bf[1] = cV[(kk * 8 + t + 4) * LDV + nt * 8 + g];
                    mma_tf32(o[0][nt], pf[0], bf);
                    mma_tf32(o[1][nt], pf[1], bf);
                }
            }
        }
        __syncthreads();
    }

    // ---- epilogue: normalize, write y (tf32 bits) ----
#pragma unroll
    for (int mt = 0; mt < 2; mt++) {
        float inv0 = 1.0f / lS[mt][0], inv1 = 1.0f / lS[mt][1];
        int r0 = rowW + mt * 16 + g;
        const size_t yr0 = ((size_t)(b * TSEQ) + r0) * CDIM + h * DH;
        const size_t yr1 = ((size_t)(b * TSEQ) + r0 + 8) * CDIM + h * DH;
#pragma unroll
        for (int nt = 0; nt < 8; nt++) {
            int c0 = nt * 8 + 2 * t;
            uint2 v0, v1;
            v0.x = f2tf32(o[mt][nt][0] * inv0); v0.y = f2tf32(o[mt][nt][1] * inv0);
            v1.x = f2tf32(o[mt][nt][2] * inv1); v1.y = f2tf32(o[mt][nt][3] * inv1);
            *(uint2*)(y + yr0 + c0) = v0;
            *(uint2*)(y + yr1 + c0) = v1;
        }
    }
}

// ---------------------------------------------------------------------------
extern "C" void kernel_launch(void* const* d_in, const int* in_sizes, int n_in,
                              void* d_out, int out_size)
{
    const float* x      = (const float*)d_in[0];
    const float* w_attn = (const float*)d_in[1];
    const float* b_attn = (const float*)d_in[2];
    const float* w_proj = (const float*)d_in[3];
    const float* b_proj = (const float*)d_in[4];
    float* out = (float*)d_out;

    unsigned *x32, *wa32, *wp32, *qkv, *yb;
    cudaGetSymbolAddress((void**)&x32, g_x32);
    cudaGetSymbolAddress((void**)&wa32, g_wa32);
    cudaGetSymbolAddress((void**)&wp32, g_wp32);
    cudaGetSymbolAddress((void**)&qkv, g_qkv);
    cudaGetSymbolAddress((void**)&yb, g_y);

    const int smem_gemm = GEMM_SMEM * (int)sizeof(unsigned);   // 71680 B
    const int smem_attn = ATTN_SMEM * (int)sizeof(unsigned);   // 106496 B
    cudaFuncSetAttribute(gemm_tf32_bias<true>,
                         cudaFuncAttributeMaxDynamicSharedMemorySize, smem_gemm);
    cudaFuncSetAttribute(gemm_tf32_bias<false>,
                         cudaFuncAttributeMaxDynamicSharedMemorySize, smem_gemm);
    cudaFuncSetAttribute(attn_flash_mma,
                         cudaFuncAttributeMaxDynamicSharedMemorySize, smem_attn);

    const int M = BSZ * TSEQ;   // 4096

    // 0) pre-convert inputs to tf32
    const int nx  = M * CDIM / 4;
    const int nwa = CDIM * 3 * CDIM / 4;
    const int nwp = CDIM * CDIM / 4;
    cvt_tf32<<<(nx  + 255) / 256, 256>>>(x,      x32,  nx);
    cvt_tf32<<<(nwa + 255) / 256, 256>>>(w_attn, wa32, nwa);
    cvt_tf32<<<(nwp + 255) / 256, 256>>>(w_proj, wp32, nwp);

    // 1) qkv = x @ w_attn + b_attn     [4096, 3072]  (tf32 out)
    gemm_tf32_bias<true><<<dim3((3 * CDIM) / 128, M / 128), 128, smem_gemm>>>(
        x32, wa32, b_attn, qkv, M, 3 * CDIM, CDIM);

    // 2) flash attention -> y (tf32)   [4096, 1024]
    attn_flash_mma<<<dim3(TSEQ / 128, HN, BSZ), 128, smem_attn>>>(qkv, yb);

    // 3) out = y @ w_proj + b_proj     [4096, 1024]  (fp32 out)
    gemm_tf32_bias<false><<<dim3(CDIM / 128, M / 128), 128, smem_gemm>>>(
        yb, wp32, b_proj, out, M, CDIM, CDIM);
}